// round 1
// baseline (speedup 1.0000x reference)
#include <cuda_runtime.h>

#define NPTS   8192
#define BATCH  4
#define TS     2048        // target points staged per chunk (32 KB smem)
#define TPB    128
#define PPT    2           // p points per thread
#define PTILE  (TPB*PPT)   // 256
#define NBLK_X (NPTS/PTILE) // 32
#define NPARTIAL (NBLK_X*BATCH*2) // 256

__device__ float g_partials[NPARTIAL];

__device__ __forceinline__ unsigned long long ffma2(unsigned long long a,
                                                    unsigned long long b,
                                                    unsigned long long c) {
    unsigned long long d;
    asm("fma.rn.f32x2 %0, %1, %2, %3;" : "=l"(d) : "l"(a), "l"(b), "l"(c));
    return d;
}
__device__ __forceinline__ unsigned long long pack2(float lo, float hi) {
    unsigned long long r;
    asm("mov.b64 %0, {%1, %2};" : "=l"(r) : "f"(lo), "f"(hi));
    return r;
}
__device__ __forceinline__ float2 unpack2(unsigned long long v) {
    float2 r;
    asm("mov.b64 {%0, %1}, %2;" : "=f"(r.x), "=f"(r.y) : "l"(v));
    return r;
}

// One block: 256 query points (p) of one (batch, direction), scans all 8192
// targets (t) through shared memory. Minimizes s = 0.5*|t|^2 - p.t  (monotone
// in d^2 = |p|^2 + 2s). Inner loop: 2 target points packed per f32x2 register.
__global__ __launch_bounds__(TPB)
void chamfer_min_kernel(const float* __restrict__ pred,
                        const float* __restrict__ targ) {
    __shared__ float4 sA[TS/2];   // (x0,x1, y0,y1) per target pair
    __shared__ float4 sB[TS/2];   // (z0,z1, h0,h1), h = 0.5*|t|^2
    __shared__ float red[TPB/32];

    const int tid = threadIdx.x;
    const int bx  = blockIdx.x;
    const int b   = blockIdx.y;
    const int dir = blockIdx.z;

    const float* P = (dir ? targ : pred) + b * 3 * NPTS;
    const float* T = (dir ? pred : targ) + b * 3 * NPTS;

    float p2[PPT];
    unsigned long long npx[PPT], npy[PPT], npz[PPT];
    float accl[PPT], acch[PPT];

#pragma unroll
    for (int p = 0; p < PPT; p++) {
        const int idx = bx * PTILE + p * TPB + tid;
        const float x = P[idx];
        const float y = P[NPTS + idx];
        const float z = P[2 * NPTS + idx];
        p2[p]  = x * x + y * y + z * z;
        npx[p] = pack2(-x, -x);
        npy[p] = pack2(-y, -y);
        npz[p] = pack2(-z, -z);
        accl[p] = 1e30f;
        acch[p] = 1e30f;
    }

    const float* Tx = T;
    const float* Ty = T + NPTS;
    const float* Tz = T + 2 * NPTS;

    for (int c = 0; c < NPTS; c += TS) {
        // ---- stage TS target points into packed-pair smem layout ----
#pragma unroll
        for (int i = tid; i < TS / 4; i += TPB) {
            const int m = c + i * 4;
            const float4 x4 = *reinterpret_cast<const float4*>(Tx + m);
            const float4 y4 = *reinterpret_cast<const float4*>(Ty + m);
            const float4 z4 = *reinterpret_cast<const float4*>(Tz + m);
            const float h0 = 0.5f * (x4.x * x4.x + y4.x * y4.x + z4.x * z4.x);
            const float h1 = 0.5f * (x4.y * x4.y + y4.y * y4.y + z4.y * z4.y);
            const float h2 = 0.5f * (x4.z * x4.z + y4.z * y4.z + z4.z * z4.z);
            const float h3 = 0.5f * (x4.w * x4.w + y4.w * y4.w + z4.w * z4.w);
            sA[2 * i]     = make_float4(x4.x, x4.y, y4.x, y4.y);
            sB[2 * i]     = make_float4(z4.x, z4.y, h0, h1);
            sA[2 * i + 1] = make_float4(x4.z, x4.w, y4.z, y4.w);
            sB[2 * i + 1] = make_float4(z4.z, z4.w, h2, h3);
        }
        __syncthreads();

        const ulonglong2* A  = reinterpret_cast<const ulonglong2*>(sA);
        const ulonglong2* Bq = reinterpret_cast<const ulonglong2*>(sB);

#pragma unroll 8
        for (int j = 0; j < TS / 2; ++j) {
            const ulonglong2 av = A[j];   // av.x = (x0,x1), av.y = (y0,y1)
            const ulonglong2 bv = Bq[j];  // bv.x = (z0,z1), bv.y = (h0,h1)
#pragma unroll
            for (int p = 0; p < PPT; p++) {
                unsigned long long s = ffma2(npx[p], av.x, bv.y);
                s = ffma2(npy[p], av.y, s);
                s = ffma2(npz[p], bv.x, s);
                const float2 sf = unpack2(s);
                accl[p] = fminf(accl[p], sf.x);
                acch[p] = fminf(acch[p], sf.y);
            }
        }
        __syncthreads();
    }

    // ---- per-thread distances, then deterministic block reduction ----
    float tsum = 0.f;
#pragma unroll
    for (int p = 0; p < PPT; p++) {
        const float smin = fminf(accl[p], acch[p]);
        const float d2   = fmaxf(fmaf(2.f, smin, p2[p]), 0.f);
        tsum += sqrtf(d2);
    }
#pragma unroll
    for (int off = 16; off > 0; off >>= 1)
        tsum += __shfl_down_sync(0xFFFFFFFFu, tsum, off);
    if ((tid & 31) == 0) red[tid >> 5] = tsum;
    __syncthreads();
    if (tid == 0) {
        float s = 0.f;
#pragma unroll
        for (int w = 0; w < TPB / 32; w++) s += red[w];
        g_partials[(blockIdx.z * BATCH + blockIdx.y) * NBLK_X + blockIdx.x] = s;
    }
}

// Deterministic final reduction of the 256 block partials.
__global__ void chamfer_reduce(float* __restrict__ out) {
    __shared__ float red[8];
    const int tid = threadIdx.x;   // 256 threads
    float v = g_partials[tid];
#pragma unroll
    for (int off = 16; off > 0; off >>= 1)
        v += __shfl_down_sync(0xFFFFFFFFu, v, off);
    if ((tid & 31) == 0) red[tid >> 5] = v;
    __syncthreads();
    if (tid == 0) {
        float s = 0.f;
#pragma unroll
        for (int w = 0; w < 8; w++) s += red[w];
        out[0] = s * (1.0f / (BATCH * NPTS));
    }
}

extern "C" void kernel_launch(void* const* d_in, const int* in_sizes, int n_in,
                              void* d_out, int out_size) {
    const float* pred = (const float*)d_in[0];
    const float* targ = (const float*)d_in[1];
    float* out = (float*)d_out;

    dim3 grid(NBLK_X, BATCH, 2);
    chamfer_min_kernel<<<grid, TPB>>>(pred, targ);
    chamfer_reduce<<<1, 256>>>(out);
}

// round 2
// speedup vs baseline: 1.1906x; 1.1906x over previous
#include <cuda_runtime.h>

#define NPTS   8192
#define BATCH  4
#define TPB    128
#define PPT    4            // p points per thread
#define PTILE  (TPB*PPT)    // 512
#define NTILE  (NPTS/PTILE) // 16 p-tiles
#define SCH    4            // target chunks
#define TS     (NPTS/SCH)   // 2048 targets per chunk (32 KB smem stage)
#define NPPTS  (2*BATCH*NPTS)   // 65536 query-point slots
#define NBLK2  256          // combine-kernel blocks

__device__ float g_smin[SCH * NPPTS];   // per-(chunk, point) partial min of s
__device__ float g_partials[NBLK2];     // per-block sums from combine

__device__ __forceinline__ unsigned long long ffma2(unsigned long long a,
                                                    unsigned long long b,
                                                    unsigned long long c) {
    unsigned long long d;
    asm("fma.rn.f32x2 %0, %1, %2, %3;" : "=l"(d) : "l"(a), "l"(b), "l"(c));
    return d;
}
__device__ __forceinline__ unsigned long long pack2(float lo, float hi) {
    unsigned long long r;
    asm("mov.b64 %0, {%1, %2};" : "=l"(r) : "f"(lo), "f"(hi));
    return r;
}
__device__ __forceinline__ float2 unpack2(unsigned long long v) {
    float2 r;
    asm("mov.b64 {%0, %1}, %2;" : "=f"(r.x), "=f"(r.y) : "l"(v));
    return r;
}

// Block = (p-tile of 512 points, batch, dir, target-chunk of 2048).
// Minimizes s = 0.5*|t|^2 - p.t over its chunk (monotone in d^2 = |p|^2+2s).
// Single smem stage (chunk == stage size), inner loop on f32x2 pairs.
__global__ __launch_bounds__(TPB)
void chamfer_min_kernel(const float* __restrict__ pred,
                        const float* __restrict__ targ) {
    __shared__ float4 sA[TS/2];   // (x0,x1, y0,y1) per target pair
    __shared__ float4 sB[TS/2];   // (z0,z1, h0,h1), h = 0.5*|t|^2

    const int tid   = threadIdx.x;
    const int ptile = blockIdx.x;        // 0..15
    const int b     = blockIdx.y;        // 0..3
    const int dir   = blockIdx.z >> 2;   // 0..1
    const int chunk = blockIdx.z & 3;    // 0..3

    const float* P = (dir ? targ : pred) + b * 3 * NPTS;
    const float* T = (dir ? pred : targ) + b * 3 * NPTS;

    // ---- stage this chunk's 2048 targets into packed-pair smem layout ----
    {
        const float* Tx = T + chunk * TS;
        const float* Ty = Tx + NPTS;
        const float* Tz = Tx + 2 * NPTS;
#pragma unroll
        for (int i = tid; i < TS / 4; i += TPB) {
            const int m = i * 4;
            const float4 x4 = *reinterpret_cast<const float4*>(Tx + m);
            const float4 y4 = *reinterpret_cast<const float4*>(Ty + m);
            const float4 z4 = *reinterpret_cast<const float4*>(Tz + m);
            const float h0 = 0.5f * (x4.x * x4.x + y4.x * y4.x + z4.x * z4.x);
            const float h1 = 0.5f * (x4.y * x4.y + y4.y * y4.y + z4.y * z4.y);
            const float h2 = 0.5f * (x4.z * x4.z + y4.z * y4.z + z4.z * z4.z);
            const float h3 = 0.5f * (x4.w * x4.w + y4.w * y4.w + z4.w * z4.w);
            sA[2 * i]     = make_float4(x4.x, x4.y, y4.x, y4.y);
            sB[2 * i]     = make_float4(z4.x, z4.y, h0, h1);
            sA[2 * i + 1] = make_float4(x4.z, x4.w, y4.z, y4.w);
            sB[2 * i + 1] = make_float4(z4.z, z4.w, h2, h3);
        }
    }

    // ---- load this thread's 4 query points ----
    unsigned long long npx[PPT], npy[PPT], npz[PPT];
    float accl[PPT], acch[PPT];
#pragma unroll
    for (int p = 0; p < PPT; p++) {
        const int idx = ptile * PTILE + p * TPB + tid;
        const float x = P[idx];
        const float y = P[NPTS + idx];
        const float z = P[2 * NPTS + idx];
        npx[p] = pack2(-x, -x);
        npy[p] = pack2(-y, -y);
        npz[p] = pack2(-z, -z);
        accl[p] = 1e30f;
        acch[p] = 1e30f;
    }
    __syncthreads();

    const ulonglong2* A  = reinterpret_cast<const ulonglong2*>(sA);
    const ulonglong2* Bq = reinterpret_cast<const ulonglong2*>(sB);

#pragma unroll 4
    for (int j = 0; j < TS / 2; ++j) {
        const ulonglong2 av = A[j];   // (x0,x1), (y0,y1)
        const ulonglong2 bv = Bq[j];  // (z0,z1), (h0,h1)
#pragma unroll
        for (int p = 0; p < PPT; p++) {
            unsigned long long s = ffma2(npx[p], av.x, bv.y);
            s = ffma2(npy[p], av.y, s);
            s = ffma2(npz[p], bv.x, s);
            const float2 sf = unpack2(s);
            accl[p] = fminf(accl[p], sf.x);
            acch[p] = fminf(acch[p], sf.y);
        }
    }

    // ---- write per-point partial min-s for this chunk ----
    const int gpbase = (dir * BATCH + b) * NPTS + ptile * PTILE;
#pragma unroll
    for (int p = 0; p < PPT; p++) {
        g_smin[chunk * NPPTS + gpbase + p * TPB + tid] =
            fminf(accl[p], acch[p]);
    }
}

// Combine: min over chunks, d = sqrt(|p|^2 + 2*s_min), deterministic block sums.
__global__ __launch_bounds__(256)
void chamfer_combine(const float* __restrict__ pred,
                     const float* __restrict__ targ) {
    __shared__ float red[8];
    const int tid = threadIdx.x;
    const int gp  = blockIdx.x * 256 + tid;

    float s = g_smin[gp];
#pragma unroll
    for (int c = 1; c < SCH; c++) s = fminf(s, g_smin[c * NPPTS + gp]);

    const int dir = gp >> 15;
    const int b   = (gp >> 13) & 3;
    const int idx = gp & (NPTS - 1);
    const float* P = (dir ? targ : pred) + b * 3 * NPTS;
    const float x = P[idx];
    const float y = P[NPTS + idx];
    const float z = P[2 * NPTS + idx];
    const float p2 = x * x + y * y + z * z;

    float d = sqrtf(fmaxf(fmaf(2.f, s, p2), 0.f));
#pragma unroll
    for (int off = 16; off > 0; off >>= 1)
        d += __shfl_down_sync(0xFFFFFFFFu, d, off);
    if ((tid & 31) == 0) red[tid >> 5] = d;
    __syncthreads();
    if (tid == 0) {
        float t = 0.f;
#pragma unroll
        for (int w = 0; w < 8; w++) t += red[w];
        g_partials[blockIdx.x] = t;
    }
}

// Deterministic final reduction of the 256 block partials.
__global__ void chamfer_reduce(float* __restrict__ out) {
    __shared__ float red[8];
    const int tid = threadIdx.x;   // 256 threads
    float v = g_partials[tid];
#pragma unroll
    for (int off = 16; off > 0; off >>= 1)
        v += __shfl_down_sync(0xFFFFFFFFu, v, off);
    if ((tid & 31) == 0) red[tid >> 5] = v;
    __syncthreads();
    if (tid == 0) {
        float s = 0.f;
#pragma unroll
        for (int w = 0; w < 8; w++) s += red[w];
        out[0] = s * (1.0f / (BATCH * NPTS));
    }
}

extern "C" void kernel_launch(void* const* d_in, const int* in_sizes, int n_in,
                              void* d_out, int out_size) {
    const float* pred = (const float*)d_in[0];
    const float* targ = (const float*)d_in[1];
    float* out = (float*)d_out;

    dim3 grid(NTILE, BATCH, 2 * SCH);   // 16 x 4 x 8 = 512 blocks
    chamfer_min_kernel<<<grid, TPB>>>(pred, targ);
    chamfer_combine<<<NBLK2, 256>>>(pred, targ);
    chamfer_reduce<<<1, 256>>>(out);
}

// round 3
// speedup vs baseline: 1.2583x; 1.0568x over previous
#include <cuda_runtime.h>

#define NPTS   8192
#define BATCH  4
#define TPB    128
#define PPT    4            // p points per thread
#define PTILE  (TPB*PPT)    // 512
#define NTILE  (NPTS/PTILE) // 16 p-tiles
#define SCH    16           // target chunks
#define TS     (NPTS/SCH)   // 512 targets per chunk (8.2 KB smem stage)
#define NPPTS  (2*BATCH*NPTS)   // 65536 query-point slots
#define NBLK2  256          // combine-kernel blocks

__device__ float g_smin[SCH * NPPTS];   // per-(chunk, point) partial min of s
__device__ float g_partials[NBLK2];     // per-block sums from combine

__device__ __forceinline__ unsigned long long ffma2(unsigned long long a,
                                                    unsigned long long b,
                                                    unsigned long long c) {
    unsigned long long d;
    asm("fma.rn.f32x2 %0, %1, %2, %3;" : "=l"(d) : "l"(a), "l"(b), "l"(c));
    return d;
}
__device__ __forceinline__ unsigned long long pack2(float lo, float hi) {
    unsigned long long r;
    asm("mov.b64 %0, {%1, %2};" : "=l"(r) : "f"(lo), "f"(hi));
    return r;
}
__device__ __forceinline__ float2 unpack2(unsigned long long v) {
    float2 r;
    asm("mov.b64 {%0, %1}, %2;" : "=f"(r.x), "=f"(r.y) : "l"(v));
    return r;
}

// Block = (p-tile of 512 points, batch, dir, target-chunk of 512).
// Minimizes s = 0.5*|t|^2 - p.t over its chunk (monotone in d^2 = |p|^2+2s).
// Single smem stage (chunk == stage size), inner loop on f32x2 pairs.
__global__ __launch_bounds__(TPB)
void chamfer_min_kernel(const float* __restrict__ pred,
                        const float* __restrict__ targ) {
    __shared__ float4 sA[TS/2];   // (x0,x1, y0,y1) per target pair
    __shared__ float4 sB[TS/2];   // (z0,z1, h0,h1), h = 0.5*|t|^2

    const int tid   = threadIdx.x;
    const int ptile = blockIdx.x;         // 0..15
    const int b     = blockIdx.y;         // 0..3
    const int dir   = blockIdx.z >> 4;    // 0..1
    const int chunk = blockIdx.z & 15;    // 0..15

    const float* P = (dir ? targ : pred) + b * 3 * NPTS;
    const float* T = (dir ? pred : targ) + b * 3 * NPTS;

    // ---- stage this chunk's 512 targets (one float4-group per thread) ----
    {
        const float* Tx = T + chunk * TS;
        const float* Ty = Tx + NPTS;
        const float* Tz = Tx + 2 * NPTS;
        const int i = tid;                // TS/4 == TPB
        const int m = i * 4;
        const float4 x4 = *reinterpret_cast<const float4*>(Tx + m);
        const float4 y4 = *reinterpret_cast<const float4*>(Ty + m);
        const float4 z4 = *reinterpret_cast<const float4*>(Tz + m);
        const float h0 = 0.5f * (x4.x * x4.x + y4.x * y4.x + z4.x * z4.x);
        const float h1 = 0.5f * (x4.y * x4.y + y4.y * y4.y + z4.y * z4.y);
        const float h2 = 0.5f * (x4.z * x4.z + y4.z * y4.z + z4.z * z4.z);
        const float h3 = 0.5f * (x4.w * x4.w + y4.w * y4.w + z4.w * z4.w);
        sA[2 * i]     = make_float4(x4.x, x4.y, y4.x, y4.y);
        sB[2 * i]     = make_float4(z4.x, z4.y, h0, h1);
        sA[2 * i + 1] = make_float4(x4.z, x4.w, y4.z, y4.w);
        sB[2 * i + 1] = make_float4(z4.z, z4.w, h2, h3);
    }

    // ---- load this thread's 4 query points ----
    unsigned long long npx[PPT], npy[PPT], npz[PPT];
    float accl[PPT], acch[PPT];
#pragma unroll
    for (int p = 0; p < PPT; p++) {
        const int idx = ptile * PTILE + p * TPB + tid;
        const float x = P[idx];
        const float y = P[NPTS + idx];
        const float z = P[2 * NPTS + idx];
        npx[p] = pack2(-x, -x);
        npy[p] = pack2(-y, -y);
        npz[p] = pack2(-z, -z);
        accl[p] = 1e30f;
        acch[p] = 1e30f;
    }
    __syncthreads();

    const ulonglong2* A  = reinterpret_cast<const ulonglong2*>(sA);
    const ulonglong2* Bq = reinterpret_cast<const ulonglong2*>(sB);

#pragma unroll 4
    for (int j = 0; j < TS / 2; ++j) {
        const ulonglong2 av = A[j];   // (x0,x1), (y0,y1)
        const ulonglong2 bv = Bq[j];  // (z0,z1), (h0,h1)
#pragma unroll
        for (int p = 0; p < PPT; p++) {
            unsigned long long s = ffma2(npx[p], av.x, bv.y);
            s = ffma2(npy[p], av.y, s);
            s = ffma2(npz[p], bv.x, s);
            const float2 sf = unpack2(s);
            accl[p] = fminf(accl[p], sf.x);
            acch[p] = fminf(acch[p], sf.y);
        }
    }

    // ---- write per-point partial min-s for this chunk ----
    const int gpbase = (dir * BATCH + b) * NPTS + ptile * PTILE;
#pragma unroll
    for (int p = 0; p < PPT; p++) {
        g_smin[chunk * NPPTS + gpbase + p * TPB + tid] =
            fminf(accl[p], acch[p]);
    }
}

// Combine: min over chunks, d = sqrt(|p|^2 + 2*s_min), deterministic block sums.
__global__ __launch_bounds__(256)
void chamfer_combine(const float* __restrict__ pred,
                     const float* __restrict__ targ) {
    __shared__ float red[8];
    const int tid = threadIdx.x;
    const int gp  = blockIdx.x * 256 + tid;

    float s = g_smin[gp];
#pragma unroll
    for (int c = 1; c < SCH; c++) s = fminf(s, g_smin[c * NPPTS + gp]);

    const int dir = gp >> 15;
    const int b   = (gp >> 13) & 3;
    const int idx = gp & (NPTS - 1);
    const float* P = (dir ? targ : pred) + b * 3 * NPTS;
    const float x = P[idx];
    const float y = P[NPTS + idx];
    const float z = P[2 * NPTS + idx];
    const float p2 = x * x + y * y + z * z;

    float d = sqrtf(fmaxf(fmaf(2.f, s, p2), 0.f));
#pragma unroll
    for (int off = 16; off > 0; off >>= 1)
        d += __shfl_down_sync(0xFFFFFFFFu, d, off);
    if ((tid & 31) == 0) red[tid >> 5] = d;
    __syncthreads();
    if (tid == 0) {
        float t = 0.f;
#pragma unroll
        for (int w = 0; w < 8; w++) t += red[w];
        g_partials[blockIdx.x] = t;
    }
}

// Deterministic final reduction of the 256 block partials.
__global__ void chamfer_reduce(float* __restrict__ out) {
    __shared__ float red[8];
    const int tid = threadIdx.x;   // 256 threads
    float v = g_partials[tid];
#pragma unroll
    for (int off = 16; off > 0; off >>= 1)
        v += __shfl_down_sync(0xFFFFFFFFu, v, off);
    if ((tid & 31) == 0) red[tid >> 5] = v;
    __syncthreads();
    if (tid == 0) {
        float s = 0.f;
#pragma unroll
        for (int w = 0; w < 8; w++) s += red[w];
        out[0] = s * (1.0f / (BATCH * NPTS));
    }
}

extern "C" void kernel_launch(void* const* d_in, const int* in_sizes, int n_in,
                              void* d_out, int out_size) {
    const float* pred = (const float*)d_in[0];
    const float* targ = (const float*)d_in[1];
    float* out = (float*)d_out;

    dim3 grid(NTILE, BATCH, 2 * SCH);   // 16 x 4 x 32 = 2048 blocks
    chamfer_min_kernel<<<grid, TPB>>>(pred, targ);
    chamfer_combine<<<NBLK2, 256>>>(pred, targ);
    chamfer_reduce<<<1, 256>>>(out);
}

// round 4
// speedup vs baseline: 1.2921x; 1.0269x over previous
#include <cuda_runtime.h>

#define NPTS   8192
#define BATCH  4
#define TPB    128
#define PPT    4            // p points per thread
#define PTILE  (TPB*PPT)    // 512
#define NTILE  (NPTS/PTILE) // 16 p-tiles
#define SCH    16           // target chunks
#define TS     (NPTS/SCH)   // 512 targets per chunk (8.2 KB smem stage)
#define NPPTS  (2*BATCH*NPTS)   // 65536 query-point slots
#define NBLK2  256          // combine-kernel blocks

__device__ float g_smin[SCH * NPPTS];   // per-(chunk, point) partial min of s
__device__ float g_partials[NBLK2];     // per-block sums from combine

__device__ __forceinline__ unsigned long long ffma2(unsigned long long a,
                                                    unsigned long long b,
                                                    unsigned long long c) {
    unsigned long long d;
    asm("fma.rn.f32x2 %0, %1, %2, %3;" : "=l"(d) : "l"(a), "l"(b), "l"(c));
    return d;
}
__device__ __forceinline__ unsigned long long pack2(float lo, float hi) {
    unsigned long long r;
    asm("mov.b64 %0, {%1, %2};" : "=l"(r) : "f"(lo), "f"(hi));
    return r;
}
__device__ __forceinline__ float2 unpack2(unsigned long long v) {
    float2 r;
    asm("mov.b64 {%0, %1}, %2;" : "=f"(r.x), "=f"(r.y) : "l"(v));
    return r;
}

// Block = (p-tile of 512 points, batch, dir, target-chunk of 512).
// Minimizes s = 0.5*|t|^2 - p.t over its chunk (monotone in d^2 = |p|^2+2s).
// Inner loop: 2 targets per f32x2 op, explicit 1-iter smem prefetch, unroll 8.
__global__ __launch_bounds__(TPB, 8)
void chamfer_min_kernel(const float* __restrict__ pred,
                        const float* __restrict__ targ) {
    __shared__ float4 sA[TS/2];   // (x0,x1, y0,y1) per target pair
    __shared__ float4 sB[TS/2];   // (z0,z1, h0,h1), h = 0.5*|t|^2

    const int tid   = threadIdx.x;
    const int ptile = blockIdx.x;         // 0..15
    const int b     = blockIdx.y;         // 0..3
    const int dir   = blockIdx.z >> 4;    // 0..1
    const int chunk = blockIdx.z & 15;    // 0..15

    const float* P = (dir ? targ : pred) + b * 3 * NPTS;
    const float* T = (dir ? pred : targ) + b * 3 * NPTS;

    // ---- stage this chunk's 512 targets (one float4-group per thread) ----
    {
        const float* Tx = T + chunk * TS;
        const float* Ty = Tx + NPTS;
        const float* Tz = Tx + 2 * NPTS;
        const int i = tid;                // TS/4 == TPB
        const int m = i * 4;
        const float4 x4 = *reinterpret_cast<const float4*>(Tx + m);
        const float4 y4 = *reinterpret_cast<const float4*>(Ty + m);
        const float4 z4 = *reinterpret_cast<const float4*>(Tz + m);
        const float h0 = 0.5f * (x4.x * x4.x + y4.x * y4.x + z4.x * z4.x);
        const float h1 = 0.5f * (x4.y * x4.y + y4.y * y4.y + z4.y * z4.y);
        const float h2 = 0.5f * (x4.z * x4.z + y4.z * y4.z + z4.z * z4.z);
        const float h3 = 0.5f * (x4.w * x4.w + y4.w * y4.w + z4.w * z4.w);
        sA[2 * i]     = make_float4(x4.x, x4.y, y4.x, y4.y);
        sB[2 * i]     = make_float4(z4.x, z4.y, h0, h1);
        sA[2 * i + 1] = make_float4(x4.z, x4.w, y4.z, y4.w);
        sB[2 * i + 1] = make_float4(z4.z, z4.w, h2, h3);
    }

    // ---- load this thread's 4 query points ----
    unsigned long long npx[PPT], npy[PPT], npz[PPT];
    float accl[PPT], acch[PPT];
#pragma unroll
    for (int p = 0; p < PPT; p++) {
        const int idx = ptile * PTILE + p * TPB + tid;
        const float x = P[idx];
        const float y = P[NPTS + idx];
        const float z = P[2 * NPTS + idx];
        npx[p] = pack2(-x, -x);
        npy[p] = pack2(-y, -y);
        npz[p] = pack2(-z, -z);
        accl[p] = 1e30f;
        acch[p] = 1e30f;
    }
    __syncthreads();

    const ulonglong2* A  = reinterpret_cast<const ulonglong2*>(sA);
    const ulonglong2* Bq = reinterpret_cast<const ulonglong2*>(sB);

    ulonglong2 av = A[0];   // prefetch registers
    ulonglong2 bv = Bq[0];

#pragma unroll 8
    for (int j = 0; j < TS / 2 - 1; ++j) {
        const ulonglong2 avc = av;
        const ulonglong2 bvc = bv;
        av = A[j + 1];      // issue next iteration's loads before compute
        bv = Bq[j + 1];
#pragma unroll
        for (int p = 0; p < PPT; p++) {
            unsigned long long s = ffma2(npx[p], avc.x, bvc.y);
            s = ffma2(npy[p], avc.y, s);
            s = ffma2(npz[p], bvc.x, s);
            const float2 sf = unpack2(s);
            accl[p] = fminf(accl[p], sf.x);
            acch[p] = fminf(acch[p], sf.y);
        }
    }
    // final iteration (data already in av/bv)
#pragma unroll
    for (int p = 0; p < PPT; p++) {
        unsigned long long s = ffma2(npx[p], av.x, bv.y);
        s = ffma2(npy[p], av.y, s);
        s = ffma2(npz[p], bv.x, s);
        const float2 sf = unpack2(s);
        accl[p] = fminf(accl[p], sf.x);
        acch[p] = fminf(acch[p], sf.y);
    }

    // ---- write per-point partial min-s for this chunk ----
    const int gpbase = (dir * BATCH + b) * NPTS + ptile * PTILE;
#pragma unroll
    for (int p = 0; p < PPT; p++) {
        g_smin[chunk * NPPTS + gpbase + p * TPB + tid] =
            fminf(accl[p], acch[p]);
    }
}

// Combine: min over chunks, d = sqrt(|p|^2 + 2*s_min), deterministic block sums.
__global__ __launch_bounds__(256)
void chamfer_combine(const float* __restrict__ pred,
                     const float* __restrict__ targ) {
    __shared__ float red[8];
    const int tid = threadIdx.x;
    const int gp  = blockIdx.x * 256 + tid;

    float s = g_smin[gp];
#pragma unroll
    for (int c = 1; c < SCH; c++) s = fminf(s, g_smin[c * NPPTS + gp]);

    const int dir = gp >> 15;
    const int b   = (gp >> 13) & 3;
    const int idx = gp & (NPTS - 1);
    const float* P = (dir ? targ : pred) + b * 3 * NPTS;
    const float x = P[idx];
    const float y = P[NPTS + idx];
    const float z = P[2 * NPTS + idx];
    const float p2 = x * x + y * y + z * z;

    float d = sqrtf(fmaxf(fmaf(2.f, s, p2), 0.f));
#pragma unroll
    for (int off = 16; off > 0; off >>= 1)
        d += __shfl_down_sync(0xFFFFFFFFu, d, off);
    if ((tid & 31) == 0) red[tid >> 5] = d;
    __syncthreads();
    if (tid == 0) {
        float t = 0.f;
#pragma unroll
        for (int w = 0; w < 8; w++) t += red[w];
        g_partials[blockIdx.x] = t;
    }
}

// Deterministic final reduction of the 256 block partials.
__global__ void chamfer_reduce(float* __restrict__ out) {
    __shared__ float red[8];
    const int tid = threadIdx.x;   // 256 threads
    float v = g_partials[tid];
#pragma unroll
    for (int off = 16; off > 0; off >>= 1)
        v += __shfl_down_sync(0xFFFFFFFFu, v, off);
    if ((tid & 31) == 0) red[tid >> 5] = v;
    __syncthreads();
    if (tid == 0) {
        float s = 0.f;
#pragma unroll
        for (int w = 0; w < 8; w++) s += red[w];
        out[0] = s * (1.0f / (BATCH * NPTS));
    }
}

extern "C" void kernel_launch(void* const* d_in, const int* in_sizes, int n_in,
                              void* d_out, int out_size) {
    const float* pred = (const float*)d_in[0];
    const float* targ = (const float*)d_in[1];
    float* out = (float*)d_out;

    dim3 grid(NTILE, BATCH, 2 * SCH);   // 16 x 4 x 32 = 2048 blocks
    chamfer_min_kernel<<<grid, TPB>>>(pred, targ);
    chamfer_combine<<<NBLK2, 256>>>(pred, targ);
    chamfer_reduce<<<1, 256>>>(out);
}